// round 10
// baseline (speedup 1.0000x reference)
#include <cuda_runtime.h>
#include <cuda_bf16.h>

#define NN 9216
#define WW 96
#define NB 8192
#define CAP 32

// Scratch (no cudaMalloc allowed). g_hist re-zeroed by scan_kernel each
// replay so every call sees clean state.
__device__ unsigned      g_hist[NB];
__device__ unsigned      g_binstart[NB];
__device__ unsigned      g_bincnt[NB];
__device__ unsigned      g_list[NB * CAP];
__device__ unsigned char g_keep[NN];

// ---------------------------------------------------------------------------
// Bucket rank stage 1 (proven R3)
// ---------------------------------------------------------------------------
__global__ void __launch_bounds__(256) hist_kernel(const float* __restrict__ cls) {
    int c = blockIdx.x * 256 + threadIdx.x;
    float s = cls[c];
    int bin = min((int)(s * 8192.0f), NB - 1);
    unsigned slot = atomicAdd(&g_hist[bin], 1u);
    if (slot < CAP) g_list[bin * CAP + slot] = (unsigned)c;
}

// ---------------------------------------------------------------------------
// Bucket rank stage 2: shuffle-based block scan (3 barriers vs 20)
// ---------------------------------------------------------------------------
__global__ void __launch_bounds__(1024) scan_kernel() {
    __shared__ unsigned wsum[32];
    const int t = threadIdx.x;
    const int lane = t & 31, wid = t >> 5;

    unsigned v[8], sum = 0;
    #pragma unroll
    for (int i = 0; i < 8; i++) { v[i] = g_hist[t * 8 + i]; sum += v[i]; }

    unsigned s = sum;                       // warp-inclusive scan of thread sums
    #pragma unroll
    for (int off = 1; off < 32; off <<= 1) {
        unsigned n = __shfl_up_sync(0xFFFFFFFFu, s, off);
        if (lane >= off) s += n;
    }
    if (lane == 31) wsum[wid] = s;
    __syncthreads();
    if (wid == 0) {
        unsigned ws = wsum[lane];
        #pragma unroll
        for (int off = 1; off < 32; off <<= 1) {
            unsigned n = __shfl_up_sync(0xFFFFFFFFu, ws, off);
            if (lane >= off) ws += n;
        }
        wsum[lane] = ws;
    }
    __syncthreads();
    unsigned run = (wid ? wsum[wid - 1] : 0u) + s - sum;  // block-exclusive prefix
    #pragma unroll
    for (int i = 0; i < 8; i++) {
        run += v[i];                         // inclusive up to bin t*8+i
        g_binstart[t * 8 + i] = NN - run;
        g_bincnt[t * 8 + i]   = v[i];
        g_hist[t * 8 + i]     = 0;           // clean for next replay
    }
}

// ---------------------------------------------------------------------------
// NMS: deterministic barrier-round engine (proven R9 logic) with REGIONAL
// warp ownership: each warp owns a compact 24x12 region (8x4 tiles of 3x3),
// so warps whose region is fully decided retire from sweeping entirely.
// Exact integer geometry (boxes 21x21; qualifiers from x%3,y%3).
// ---------------------------------------------------------------------------
__device__ __forceinline__ void set_bit_s(unsigned* arr, int x, int y) {
    int p = x + 2;
    atomicOr(&arr[y * 4 + (p >> 5)], 1u << (p & 31));
}

__global__ void __launch_bounds__(1024, 1) nms_kernel(const float* __restrict__ cls) {
    __shared__ float    sc[NN];
    __shared__ unsigned dec1[WW * 4], kept1[WW * 4], dec2[WW * 4], kept2[WW * 4];

    const int t    = threadIdx.x;
    const int lane = t & 31, wid = t >> 5;
    // Regional mapping: warp grid 4x8; within warp, lane grid 8x4 tiles.
    const int TX = (wid & 3) * 8 + (lane & 7);    // 0..31
    const int TY = (wid >> 2) * 4 + (lane >> 3);  // 0..31
    const int x0 = 3 * TX, y0 = 3 * TY;
    const int w  = x0 >> 5, sh = x0 & 31;

    if (t < WW * 4) { dec1[t] = 0; kept1[t] = 0; dec2[t] = 0; kept2[t] = 0; }
    #pragma unroll
    for (int k = 0; k < 9; k++) sc[t + k * 1024] = cls[t + k * 1024];
    __syncthreads();

    // ---- Build masks + init invalid cells ----
    unsigned m1[9];
    unsigned long long m2all = 0;   // 4 bits/cell: up,left,right,down (thr 0.7)
    unsigned pend = 0;
    #pragma unroll
    for (int k = 0; k < 9; k++) {
        int ry = k / 3, cx = k % 3;
        int x = x0 + cx, y = y0 + ry;
        int c = y * WW + x;
        float s = sc[c];
        unsigned mm1 = 0, n2 = 0;
        if (s > 0.6f) {
            pend |= 1u << k;
            int xm = x % 3, ym = y % 3;
            #define EARLIER(n) (sc[(n)] > s || (sc[(n)] == s && (n) < c))
            if (x > 0  && EARLIER(c - 1))  { mm1 |= 1u << 11; if (xm != 2) n2 |= 2u; }
            if (x < 95 && EARLIER(c + 1))  { mm1 |= 1u << 13; if (xm != 1) n2 |= 4u; }
            if (y > 0  && EARLIER(c - 96)) { mm1 |= 1u << 7;  if (ym != 2) n2 |= 1u; }
            if (y < 95 && EARLIER(c + 96)) { mm1 |= 1u << 17; if (ym != 1) n2 |= 8u; }
            if (x > 1  && xm == 1 && EARLIER(c - 2))   mm1 |= 1u << 10;
            if (x < 94 && xm == 2 && EARLIER(c + 2))   mm1 |= 1u << 14;
            if (y > 1  && ym == 1 && EARLIER(c - 192)) mm1 |= 1u << 2;
            if (y < 94 && ym == 2 && EARLIER(c + 192)) mm1 |= 1u << 22;
            bool sxp4 = (xm == 1), sxm4 = (xm == 2), syp4 = (ym == 1), sym4 = (ym == 2);
            if (x > 0  && y > 0  && !(sxm4 && sym4) && EARLIER(c - 97)) mm1 |= 1u << 6;
            if (x < 95 && y > 0  && !(sxp4 && sym4) && EARLIER(c - 95)) mm1 |= 1u << 8;
            if (x > 0  && y < 95 && !(sxm4 && syp4) && EARLIER(c + 95)) mm1 |= 1u << 16;
            if (x < 95 && y < 95 && !(sxp4 && syp4) && EARLIER(c + 97)) mm1 |= 1u << 18;
            #undef EARLIER
        } else {
            set_bit_s(dec1, x, y);
            set_bit_s(dec2, x, y);
        }
        m1[k] = mm1;
        m2all |= (unsigned long long)n2 << (4 * k);
    }
    __syncthreads();

    unsigned p1 = pend, p2 = pend, keep9 = 0;

    // ---- Barrier rounds (2 sweeps per round) ----
    for (;;) {
        #pragma unroll
        for (int rep = 0; rep < 2; rep++) {
            if (p1) {
                unsigned dw[7], kw[7];
                #pragma unroll
                for (int r = 0; r < 7; r++) {
                    int ry = y0 - 2 + r;
                    if ((unsigned)ry < WW) {
                        int base = ry * 4 + w;
                        dw[r] = __funnelshift_r(dec1[base],  dec1[base + 1],  sh) & 0x1FFu;
                        kw[r] = __funnelshift_r(kept1[base], kept1[base + 1], sh) & 0x1FFu;
                    } else { dw[r] = 0; kw[r] = 0; }
                }
                #pragma unroll
                for (int k = 0; k < 9; k++) {
                    if (!(p1 & (1u << k))) continue;
                    int ry = k / 3, cx = k % 3;
                    unsigned mm = m1[k], supp = 0, und = 0;
                    #pragma unroll
                    for (int r = 0; r < 5; r++) {
                        unsigned mrow = (mm >> (5 * r)) & 31u;
                        supp |= mrow & (kw[ry + r] >> cx);
                        und  |= mrow & ((~dw[ry + r]) >> cx);
                    }
                    int x = x0 + cx, y = y0 + ry;
                    if (supp) {
                        set_bit_s(dec1, x, y); set_bit_s(dec2, x, y);
                        dw[ry + 2] |= 1u << (cx + 2);
                        p1 &= ~(1u << k); p2 &= ~(1u << k);
                    } else if (!und) {
                        set_bit_s(dec1, x, y); set_bit_s(kept1, x, y);
                        dw[ry + 2] |= 1u << (cx + 2);
                        kw[ry + 2] |= 1u << (cx + 2);
                        p1 &= ~(1u << k);
                    }
                }
            }
            unsigned ready = p2 & ~p1;
            if (ready) {
                unsigned dw[7], kw[7];
                #pragma unroll
                for (int r = 0; r < 7; r++) {
                    int ry = y0 - 2 + r;
                    if ((unsigned)ry < WW) {
                        int base = ry * 4 + w;
                        dw[r] = __funnelshift_r(dec2[base],  dec2[base + 1],  sh) & 0x1FFu;
                        kw[r] = __funnelshift_r(kept2[base], kept2[base + 1], sh) & 0x1FFu;
                    } else { dw[r] = 0; kw[r] = 0; }
                }
                #pragma unroll
                for (int k = 0; k < 9; k++) {
                    if (!(ready & (1u << k))) continue;
                    int ry = k / 3, cx = k % 3;
                    unsigned n2 = (unsigned)(m2all >> (4 * k)) & 15u;
                    unsigned supp =
                          ((n2 >> 0) & (kw[ry + 1] >> (cx + 2)))
                        | ((n2 >> 1) & (kw[ry + 2] >> (cx + 1)))
                        | ((n2 >> 2) & (kw[ry + 2] >> (cx + 3)))
                        | ((n2 >> 3) & (kw[ry + 3] >> (cx + 2)));
                    unsigned und =
                          ((n2 >> 0) & ((~dw[ry + 1]) >> (cx + 2)))
                        | ((n2 >> 1) & ((~dw[ry + 2]) >> (cx + 1)))
                        | ((n2 >> 2) & ((~dw[ry + 2]) >> (cx + 3)))
                        | ((n2 >> 3) & ((~dw[ry + 3]) >> (cx + 2)));
                    int x = x0 + cx, y = y0 + ry;
                    if (supp & 1u) {
                        set_bit_s(dec2, x, y);
                        dw[ry + 2] |= 1u << (cx + 2);
                        p2 &= ~(1u << k);
                    } else if (!(und & 1u)) {
                        set_bit_s(dec2, x, y); set_bit_s(kept2, x, y);
                        dw[ry + 2] |= 1u << (cx + 2);
                        kw[ry + 2] |= 1u << (cx + 2);
                        keep9 |= 1u << k;
                        p2 &= ~(1u << k);
                    }
                }
            }
        }
        if (__syncthreads_and((p1 | p2) == 0)) break;
    }

    #pragma unroll
    for (int k = 0; k < 9; k++) {
        int c = (y0 + k / 3) * WW + x0 + (k % 3);
        g_keep[c] = (keep9 >> k) & 1u;
    }
}

// ---------------------------------------------------------------------------
// Epilogue: cnt==1 fast path (singleton bin => the list entry is this cell),
// wider grid for latency hiding.
// ---------------------------------------------------------------------------
__global__ void __launch_bounds__(128) epi_kernel(const float* __restrict__ cls,
                                                  const float* __restrict__ reg,
                                                  float* __restrict__ out) {
    const int c = blockIdx.x * 128 + threadIdx.x;
    float s  = cls[c];
    int bin  = min((int)(s * 8192.0f), NB - 1);
    unsigned rank = g_binstart[bin];
    unsigned cnt  = min(g_bincnt[bin], (unsigned)CAP);
    if (cnt > 1u) {
        for (unsigned j = 0; j < cnt; j++) {
            int idx = (int)g_list[bin * CAP + j];
            float sj = cls[idx];
            rank += (sj > s) || (sj == s && idx < c);
        }
    }
    float kq = g_keep[c] ? 1.0f : 0.0f;
    int x = c % WW, y = c / WW;
    float X1 = rintf((2.0f * x) / 0.6f);
    float X2 = rintf((2.0f * x + 12.0f) / 0.6f);
    float Y1 = rintf((2.0f * y) / 0.6f);
    float Y2 = rintf((2.0f * y + 12.0f) / 0.6f);
    float bw = X2 - X1 + 1.0f;
    float bh = Y2 - Y1 + 1.0f;
    float4 d = ((const float4*)reg)[c];
    float* o = out + (int)rank * 5;
    o[0] = (X1 + d.x * bw) * kq;
    o[1] = (Y1 + d.y * bh) * kq;
    o[2] = (X2 + d.z * bw) * kq;
    o[3] = (Y2 + d.w * bh) * kq;
    o[4] = s * kq;
}

extern "C" void kernel_launch(void* const* d_in, const int* in_sizes, int n_in,
                              void* d_out, int out_size) {
    const float* cls = (const float*)d_in[0];
    const float* reg = (const float*)d_in[1];
    if (n_in >= 2 && in_sizes[0] > in_sizes[1]) {   // defensive: metadata order
        const float* t = cls; cls = reg; reg = t;
    }
    float* out = (float*)d_out;

    hist_kernel<<<36, 256>>>(cls);
    scan_kernel<<<1, 1024>>>();
    nms_kernel<<<1, 1024>>>(cls);
    epi_kernel<<<72, 128>>>(cls, reg, out);
}